// round 10
// baseline (speedup 1.0000x reference)
#include <cuda_runtime.h>

// Mask2Former post-processing, fused (R5: wave-balanced 7 CTA/SM residency,
// lerp algebra rewritten as c + w*(t-c), pre-packed prob tables in smem):
//   out[b,c,H,W] = sum_q softmax(cls[b,q,:])[c] * sigmoid(bilinear4x(masks[b,q]))
// sigmoid(x) = 0.5 + 0.5*tanh(x/2); /2 folded into horizontal lerp, +0.5*sum(p)
// folded into the epilogue. Thread = 4x2 output px (half input cell), 2x3
// clamped neighborhood, packed f32x2 math, 8 tanh.approx per q.

#define Q   100
#define HI  128
#define WI  128
#define HO  512
#define WO  512

using u64 = unsigned long long;

__device__ __forceinline__ u64 pk2(float lo, float hi) {
    u64 r; asm("mov.b64 %0, {%1, %2};" : "=l"(r) : "f"(lo), "f"(hi)); return r;
}
__device__ __forceinline__ void upk2(float& lo, float& hi, u64 p) {
    asm("mov.b64 {%0, %1}, %2;" : "=f"(lo), "=f"(hi) : "l"(p));
}
__device__ __forceinline__ u64 fma2(u64 a, u64 b, u64 c) {
    u64 d; asm("fma.rn.f32x2 %0, %1, %2, %3;" : "=l"(d) : "l"(a), "l"(b), "l"(c)); return d;
}
__device__ __forceinline__ u64 add2(u64 a, u64 b) {
    u64 d; asm("add.rn.f32x2 %0, %1, %2;" : "=l"(d) : "l"(a), "l"(b)); return d;
}
__device__ __forceinline__ float tanhap(float x) {
    float y; asm("tanh.approx.f32 %0, %1;" : "=f"(y) : "f"(x)); return y;
}

// packed constants
#define C1875 0x3E4000003E400000ULL   // (0.1875, 0.1875) = 0.5*0.375
#define C0625 0x3D8000003D800000ULL   // (0.0625, 0.0625) = 0.5*0.125
#define CNEG1 0xBF800000BF800000ULL   // (-1, -1)

__global__ __launch_bounds__(128, 7)
void m2f_fused_kernel(const float* __restrict__ cls,    // [8,Q,3]
                      const float* __restrict__ masks,  // [8,Q,128,128]
                      float* __restrict__ out)          // [8,2,512,512]
{
    __shared__ u64 pcA[Q];   // (p0, p0)
    __shared__ u64 pcB[Q];   // (p1, p1)
    __shared__ u64 pcP[Q];   // (p0, p1)

    const int b    = blockIdx.z;
    const int tid  = threadIdx.x;
    const int lane = tid & 31;
    const int w    = tid >> 5;

    // --- class softmax (keep classes 0,1 of 3) ---
    if (tid < Q) {
        const float* cl = cls + ((size_t)b * Q + tid) * 3;
        float a0 = cl[0], a1 = cl[1], a2 = cl[2];
        float mx = fmaxf(a0, fmaxf(a1, a2));
        float e0 = __expf(a0 - mx);
        float e1 = __expf(a1 - mx);
        float e2 = __expf(a2 - mx);
        float inv = __frcp_rn(e0 + e1 + e2);
        float p0 = e0 * inv, p1 = e1 * inv;
        pcA[tid] = pk2(p0, p0);
        pcB[tid] = pk2(p1, p1);
        pcP[tid] = pk2(p0, p1);
    }
    __syncthreads();

    // this thread's input cell and half (h=0: top 2 output rows, h=1: bottom 2)
    const int gx = blockIdx.x * 32 + lane;          // 0..127
    const int gy = blockIdx.y * 2 + (w >> 1);       // 0..127
    const int h  = w & 1;

    // q-invariant clamped offsets: far row + center row, 3 cols each
    const int xm = max(gx - 1, 0), xp = min(gx + 1, WI - 1);
    const int yf = h ? min(gy + 1, HI - 1) : max(gy - 1, 0);
    const int rF = yf * WI, rC = gy * WI;
    const int oF0 = rF + xm, oF1 = rF + gx, oF2 = rF + xp;
    const int oC0 = rC + xm, oC1 = rC + gx, oC2 = rC + xp;

    // vertical far-row weights per output row; lerp form c + w*(t-c)
    const float wf0 = h ? 0.125f : 0.375f;
    const float wf1 = h ? 0.375f : 0.125f;
    const u64 WF0 = pk2(wf0, wf0);
    const u64 WF1 = pk2(wf1, wf1);

    const float* mb = masks + (size_t)b * Q * HI * WI;

    // acc[row][pair][class]; pair0 = (px0,px3), pair1 = (px1,px2)
    u64 acc[2][2][2];
    #pragma unroll
    for (int r = 0; r < 2; r++)
        #pragma unroll
        for (int pr = 0; pr < 2; pr++) {
            acc[r][pr][0] = 0ULL;
            acc[r][pr][1] = 0ULL;
        }
    u64 Pp = 0ULL;   // (sum p0, sum p1)

    #pragma unroll 2
    for (int q = 0; q < Q; ++q, mb += HI * WI) {
        // 2x3 neighborhood
        const float fl = __ldg(mb + oF0), fm = __ldg(mb + oF1), fr = __ldg(mb + oF2);
        const float cl2 = __ldg(mb + oC0), cm = __ldg(mb + oC1), cr = __ldg(mb + oC2);

        const u64 p00 = pcA[q];
        const u64 p11 = pcB[q];
        Pp = add2(Pp, pcP[q]);

        // horizontal lerps, 0.5 folded in:
        //   A = 0.1875*(l,r) + 0.3125*m = 0.5m + 0.1875*((l,r)-m)
        //   B = 0.0625*(l,r) + 0.4375*m = 0.5m + 0.0625*((l,r)-m)
        const float hfm = 0.5f * fm, hcm = 0.5f * cm;
        const u64 fd  = pk2(fl - fm, fr - fm);
        const u64 cd  = pk2(cl2 - cm, cr - cm);
        const u64 HFM = pk2(hfm, hfm);
        const u64 HCM = pk2(hcm, hcm);
        const u64 FA = fma2(C1875, fd, HFM);
        const u64 FB = fma2(C0625, fd, HFM);
        const u64 CA = fma2(C1875, cd, HCM);
        const u64 CB = fma2(C0625, cd, HCM);

        // vertical lerps: v = C + wf*(T - C); then tanh + packed accumulate
        #pragma unroll
        for (int pr = 0; pr < 2; pr++) {
            const u64 T = pr ? FB : FA;     // far row
            const u64 C = pr ? CB : CA;     // center row
            const u64 d  = fma2(CNEG1, C, T);       // T - C
            const u64 v0 = fma2(WF0, d, C);
            const u64 v1 = fma2(WF1, d, C);
            float a, bb;
            upk2(a, bb, v0);
            const u64 t0 = pk2(tanhap(a), tanhap(bb));
            upk2(a, bb, v1);
            const u64 t1 = pk2(tanhap(a), tanhap(bb));
            acc[0][pr][0] = fma2(p00, t0, acc[0][pr][0]);
            acc[0][pr][1] = fma2(p11, t0, acc[0][pr][1]);
            acc[1][pr][0] = fma2(p00, t1, acc[1][pr][0]);
            acc[1][pr][1] = fma2(p11, t1, acc[1][pr][1]);
        }
    }

    // --- epilogue: out = 0.5*(acc + P) ---
    float P0, P1;
    upk2(P0, P1, Pp);
    const int oy = gy * 4 + h * 2;
    const int ox = gx * 4;
    #pragma unroll
    for (int c = 0; c < 2; c++) {
        const float P = c ? P1 : P0;
        float* ob = out + (((size_t)(b * 2 + c) * HO + oy) * WO + ox);
        #pragma unroll
        for (int r = 0; r < 2; r++) {
            float x0, x3, x1, x2;
            upk2(x0, x3, acc[r][0][c]);
            upk2(x1, x2, acc[r][1][c]);
            float4 val = make_float4(0.5f * (x0 + P), 0.5f * (x1 + P),
                                     0.5f * (x2 + P), 0.5f * (x3 + P));
            *reinterpret_cast<float4*>(ob + r * WO) = val;
        }
    }
}

extern "C" void kernel_launch(void* const* d_in, const int* in_sizes, int n_in,
                              void* d_out, int out_size)
{
    const float* cls   = (const float*)d_in[0];
    const float* masks = (const float*)d_in[1];
    if (n_in >= 2 && in_sizes[0] > in_sizes[1]) {
        const float* t = cls; cls = masks; masks = t;
    }
    float* out = (float*)d_out;

    dim3 grid(4, 64, 8);   // 4x32 cells wide, 64 blocks of 2 cell-rows, 8 batches
    m2f_fused_kernel<<<grid, 128>>>(cls, masks, out);
}

// round 15
// speedup vs baseline: 1.0615x; 1.0615x over previous
#include <cuda_runtime.h>

// Mask2Former post-processing, fused (R6: explicit software-pipelined register
// prefetch — loads for q+1 issue before compute of q, hiding the first-touch
// L2/DRAM latency that capped MUFU at ~66%):
//   out[b,c,H,W] = sum_q softmax(cls[b,q,:])[c] * sigmoid(bilinear4x(masks[b,q]))
// sigmoid(x) = 0.5 + 0.5*tanh(x/2); /2 folded into horizontal lerp, +0.5*sum(p)
// folded into the epilogue. Thread = 4x2 output px (half input cell), 2x3
// clamped neighborhood, packed f32x2 math, 8 tanh.approx per q.

#define Q   100
#define HI  128
#define WI  128
#define HO  512
#define WO  512

using u64 = unsigned long long;

__device__ __forceinline__ u64 pk2(float lo, float hi) {
    u64 r; asm("mov.b64 %0, {%1, %2};" : "=l"(r) : "f"(lo), "f"(hi)); return r;
}
__device__ __forceinline__ void upk2(float& lo, float& hi, u64 p) {
    asm("mov.b64 {%0, %1}, %2;" : "=f"(lo), "=f"(hi) : "l"(p));
}
__device__ __forceinline__ u64 fma2(u64 a, u64 b, u64 c) {
    u64 d; asm("fma.rn.f32x2 %0, %1, %2, %3;" : "=l"(d) : "l"(a), "l"(b), "l"(c)); return d;
}
__device__ __forceinline__ u64 add2(u64 a, u64 b) {
    u64 d; asm("add.rn.f32x2 %0, %1, %2;" : "=l"(d) : "l"(a), "l"(b)); return d;
}
__device__ __forceinline__ float tanhap(float x) {
    float y; asm("tanh.approx.f32 %0, %1;" : "=f"(y) : "f"(x)); return y;
}

// packed constants
#define C1875 0x3E4000003E400000ULL   // (0.1875, 0.1875) = 0.5*0.375
#define C0625 0x3D8000003D800000ULL   // (0.0625, 0.0625) = 0.5*0.125
#define CNEG1 0xBF800000BF800000ULL   // (-1, -1)

__global__ __launch_bounds__(128, 7)
void m2f_fused_kernel(const float* __restrict__ cls,    // [8,Q,3]
                      const float* __restrict__ masks,  // [8,Q,128,128]
                      float* __restrict__ out)          // [8,2,512,512]
{
    __shared__ u64 pcA[Q];   // (p0, p0)
    __shared__ u64 pcB[Q];   // (p1, p1)
    __shared__ u64 pcP[Q];   // (p0, p1)

    const int b    = blockIdx.z;
    const int tid  = threadIdx.x;
    const int lane = tid & 31;
    const int w    = tid >> 5;

    // --- class softmax (keep classes 0,1 of 3) ---
    if (tid < Q) {
        const float* cl = cls + ((size_t)b * Q + tid) * 3;
        float a0 = cl[0], a1 = cl[1], a2 = cl[2];
        float mx = fmaxf(a0, fmaxf(a1, a2));
        float e0 = __expf(a0 - mx);
        float e1 = __expf(a1 - mx);
        float e2 = __expf(a2 - mx);
        float inv = __frcp_rn(e0 + e1 + e2);
        float p0 = e0 * inv, p1 = e1 * inv;
        pcA[tid] = pk2(p0, p0);
        pcB[tid] = pk2(p1, p1);
        pcP[tid] = pk2(p0, p1);
    }
    __syncthreads();

    // this thread's input cell and half (h=0: top 2 output rows, h=1: bottom 2)
    const int gx = blockIdx.x * 32 + lane;          // 0..127
    const int gy = blockIdx.y * 2 + (w >> 1);       // 0..127
    const int h  = w & 1;

    // q-invariant clamped offsets: far row + center row, 3 cols each
    const int xm = max(gx - 1, 0), xp = min(gx + 1, WI - 1);
    const int yf = h ? min(gy + 1, HI - 1) : max(gy - 1, 0);
    const int rF = yf * WI, rC = gy * WI;
    const int oF0 = rF + xm, oF1 = rF + gx, oF2 = rF + xp;
    const int oC0 = rC + xm, oC1 = rC + gx, oC2 = rC + xp;

    // vertical far-row weights per output row; lerp form c + w*(t-c)
    const float wf0 = h ? 0.125f : 0.375f;
    const float wf1 = h ? 0.375f : 0.125f;
    const u64 WF0 = pk2(wf0, wf0);
    const u64 WF1 = pk2(wf1, wf1);

    const float* mb = masks + (size_t)b * Q * HI * WI;

    // acc[row][pair][class]; pair0 = (px0,px3), pair1 = (px1,px2)
    u64 acc[2][2][2];
    #pragma unroll
    for (int r = 0; r < 2; r++)
        #pragma unroll
        for (int pr = 0; pr < 2; pr++) {
            acc[r][pr][0] = 0ULL;
            acc[r][pr][1] = 0ULL;
        }
    u64 Pp = 0ULL;   // (sum p0, sum p1)

    // --- software pipeline: prefetch q=0 ---
    float nfl = __ldg(mb + oF0), nfm = __ldg(mb + oF1), nfr = __ldg(mb + oF2);
    float ncl = __ldg(mb + oC0), ncm = __ldg(mb + oC1), ncr = __ldg(mb + oC2);

    for (int q = 0; q < Q; ++q) {
        // consume prefetched values
        const float fl = nfl, fm = nfm, fr = nfr;
        const float cl2 = ncl, cm = ncm, cr = ncr;

        // issue next iteration's loads FIRST (in-order issue: these must
        // precede the tanh chain to overlap L2/DRAM latency with compute)
        if (q + 1 < Q) {
            const float* mn = mb + (size_t)(q + 1) * HI * WI;
            nfl = __ldg(mn + oF0); nfm = __ldg(mn + oF1); nfr = __ldg(mn + oF2);
            ncl = __ldg(mn + oC0); ncm = __ldg(mn + oC1); ncr = __ldg(mn + oC2);
        }

        const u64 p00 = pcA[q];
        const u64 p11 = pcB[q];
        Pp = add2(Pp, pcP[q]);

        // horizontal lerps, 0.5 folded in:
        //   A = 0.5m + 0.1875*((l,r)-m),  B = 0.5m + 0.0625*((l,r)-m)
        const float hfm = 0.5f * fm, hcm = 0.5f * cm;
        const u64 fd  = pk2(fl - fm, fr - fm);
        const u64 cd  = pk2(cl2 - cm, cr - cm);
        const u64 HFM = pk2(hfm, hfm);
        const u64 HCM = pk2(hcm, hcm);
        const u64 FA = fma2(C1875, fd, HFM);
        const u64 FB = fma2(C0625, fd, HFM);
        const u64 CA = fma2(C1875, cd, HCM);
        const u64 CB = fma2(C0625, cd, HCM);

        // vertical lerps: v = C + wf*(T - C); then tanh + packed accumulate
        #pragma unroll
        for (int pr = 0; pr < 2; pr++) {
            const u64 T = pr ? FB : FA;     // far row
            const u64 C = pr ? CB : CA;     // center row
            const u64 d  = fma2(CNEG1, C, T);       // T - C
            const u64 v0 = fma2(WF0, d, C);
            const u64 v1 = fma2(WF1, d, C);
            float a, bb;
            upk2(a, bb, v0);
            const u64 t0 = pk2(tanhap(a), tanhap(bb));
            upk2(a, bb, v1);
            const u64 t1 = pk2(tanhap(a), tanhap(bb));
            acc[0][pr][0] = fma2(p00, t0, acc[0][pr][0]);
            acc[0][pr][1] = fma2(p11, t0, acc[0][pr][1]);
            acc[1][pr][0] = fma2(p00, t1, acc[1][pr][0]);
            acc[1][pr][1] = fma2(p11, t1, acc[1][pr][1]);
        }
    }

    // --- epilogue: out = 0.5*(acc + P) ---
    float P0, P1;
    upk2(P0, P1, Pp);
    const int oy = gy * 4 + h * 2;
    const int ox = gx * 4;
    #pragma unroll
    for (int c = 0; c < 2; c++) {
        const float P = c ? P1 : P0;
        float* ob = out + (((size_t)(b * 2 + c) * HO + oy) * WO + ox);
        #pragma unroll
        for (int r = 0; r < 2; r++) {
            float x0, x3, x1, x2;
            upk2(x0, x3, acc[r][0][c]);
            upk2(x1, x2, acc[r][1][c]);
            float4 val = make_float4(0.5f * (x0 + P), 0.5f * (x1 + P),
                                     0.5f * (x2 + P), 0.5f * (x3 + P));
            *reinterpret_cast<float4*>(ob + r * WO) = val;
        }
    }
}

extern "C" void kernel_launch(void* const* d_in, const int* in_sizes, int n_in,
                              void* d_out, int out_size)
{
    const float* cls   = (const float*)d_in[0];
    const float* masks = (const float*)d_in[1];
    if (n_in >= 2 && in_sizes[0] > in_sizes[1]) {
        const float* t = cls; cls = masks; masks = t;
    }
    float* out = (float*)d_out;

    dim3 grid(4, 64, 8);   // 4x32 cells wide, 64 blocks of 2 cell-rows, 8 batches
    m2f_fused_kernel<<<grid, 128>>>(cls, masks, out);
}